// round 9
// baseline (speedup 1.0000x reference)
#include <cuda_runtime.h>
#include <cuda_fp16.h>
#include <cstdint>

#define NN 100000
#define NE 1600000
#define DD 128
#define SCAN_BLOCKS ((NN + 255) / 256)       // 391
#define SCALE_BLOCKS ((NN * 16 + 255) / 256) // 6250

// ---------------- scratch (zero-initialized at module load) ----------------
__device__ int   g_cnt[NN];
__device__ int   g_rowstart[NN + 1];
__device__ int   g_cursor[NN];
__device__ float g_dinv[NN];
__device__ int   g_src_sorted[NE];
__device__ unsigned long long g_bpack[SCAN_BLOCKS];
__device__ int   g_ticket;
__device__ uint4 g_h0h[(size_t)NN * 16];  // x_hat  fp16 (8 halves / uint4)
__device__ uint4 g_h1h[(size_t)NN * 16];  // h1_hat fp16

// ---------------- helpers ----------------
__device__ __forceinline__ void unpack8(uint4 u, float f[8]) {
    float2 a = __half22float2(*(__half2*)&u.x);
    float2 b = __half22float2(*(__half2*)&u.y);
    float2 c = __half22float2(*(__half2*)&u.z);
    float2 d = __half22float2(*(__half2*)&u.w);
    f[0] = a.x; f[1] = a.y; f[2] = b.x; f[3] = b.y;
    f[4] = c.x; f[5] = c.y; f[6] = d.x; f[7] = d.y;
}
__device__ __forceinline__ uint4 pack8(const float f[8], float s) {
    __half2 a = __floats2half2_rn(f[0] * s, f[1] * s);
    __half2 b = __floats2half2_rn(f[2] * s, f[3] * s);
    __half2 c = __floats2half2_rn(f[4] * s, f[5] * s);
    __half2 d = __floats2half2_rn(f[6] * s, f[7] * s);
    uint4 u;
    u.x = *(unsigned*)&a; u.y = *(unsigned*)&b;
    u.z = *(unsigned*)&c; u.w = *(unsigned*)&d;
    return u;
}
// add fp16-pairwise sum of (a,b) into fp32 acc
__device__ __forceinline__ void accum_pair(uint4 a, uint4 b, float acc[8]) {
    __half2 hx = __hadd2(*(__half2*)&a.x, *(__half2*)&b.x);
    __half2 hy = __hadd2(*(__half2*)&a.y, *(__half2*)&b.y);
    __half2 hz = __hadd2(*(__half2*)&a.z, *(__half2*)&b.z);
    __half2 hw = __hadd2(*(__half2*)&a.w, *(__half2*)&b.w);
    float2 fx = __half22float2(hx);
    float2 fy = __half22float2(hy);
    float2 fz = __half22float2(hz);
    float2 fw = __half22float2(hw);
    acc[0] += fx.x; acc[1] += fx.y; acc[2] += fy.x; acc[3] += fy.y;
    acc[4] += fz.x; acc[5] += fz.y; acc[6] += fw.x; acc[7] += fw.y;
}
__device__ __forceinline__ void accum_one(uint4 u, float acc[8]) {
    float f[8];
    unpack8(u, f);
#pragma unroll
    for (int j = 0; j < 8; j++) acc[j] += f[j];
}

// shared gather loop: acc += sum over edges [e,e1) of hin[src]
__device__ __forceinline__ void gather_accum(const uint4* __restrict__ hin,
                                             int lane, int e, int e1, float acc[8]) {
    for (; e + 8 <= e1; e += 8) {
        int s[8];
#pragma unroll
        for (int k = 0; k < 8; k++) s[k] = __ldg(&g_src_sorted[e + k]);
        uint4 u[8];
#pragma unroll
        for (int k = 0; k < 8; k++) u[k] = __ldg(&hin[(size_t)s[k] * 16 + lane]);
#pragma unroll
        for (int p = 0; p < 4; p++) accum_pair(u[2 * p], u[2 * p + 1], acc);
    }
    for (; e + 2 <= e1; e += 2) {
        int s0 = __ldg(&g_src_sorted[e]);
        int s1 = __ldg(&g_src_sorted[e + 1]);
        uint4 u0 = __ldg(&hin[(size_t)s0 * 16 + lane]);
        uint4 u1 = __ldg(&hin[(size_t)s1 * 16 + lane]);
        accum_pair(u0, u1, acc);
    }
    if (e < e1) {
        int s = __ldg(&g_src_sorted[e]);
        accum_one(__ldg(&hin[(size_t)s * 16 + lane]), acc);
    }
}

// block-local dtype detect: int64 little-endian => all odd 32-bit words zero
__device__ __forceinline__ int block_is64(const unsigned int* e) {
    unsigned m = 0;
    int t = threadIdx.x;
    for (int k = t; k < 1024; k += 256) m |= e[2 * k + 1];
    return __syncthreads_or((int)m) == 0;
}
__device__ __forceinline__ int load_idx(const void* ei, long long pos, int is64) {
    if (is64) return (int)((const long long*)ei)[pos];
    return ((const int*)ei)[pos];
}

// ---------------- 1) histogram of dst ----------------
__global__ void __launch_bounds__(256) hist_kernel(const void* __restrict__ ei) {
    int is64 = block_is64((const unsigned int*)ei);
    int i = blockIdx.x * blockDim.x + threadIdx.x;
    if (i < NE) {
        int d = load_idx(ei, (long long)NE + i, is64);
        if ((unsigned)d < (unsigned)NN) atomicAdd(&g_cnt[d], 1);
    }
}

// ---------------- 2) fused: decoupled-lookback scan | x prescale ----------
__global__ void __launch_bounds__(256) scan_scale_kernel(const float4* __restrict__ x) {
    int t = threadIdx.x;
    if (blockIdx.x < SCAN_BLOCKS) {
        __shared__ int s_b;
        __shared__ int wsum[8];
        __shared__ int s_off;
        if (t == 0) s_b = atomicAdd(&g_ticket, 1);
        __syncthreads();
        int b = s_b;
        int lane = t & 31, wid = t >> 5;
        int i = b * 256 + t;

        int c = (i < NN) ? g_cnt[i] : 0;
        int v = c;
#pragma unroll
        for (int o = 1; o < 32; o <<= 1) {
            int n = __shfl_up_sync(0xffffffffu, v, o);
            if (lane >= o) v += n;
        }
        if (lane == 31) wsum[wid] = v;
        __syncthreads();
        if (t < 8) {
            int w = wsum[t];
#pragma unroll
            for (int o = 1; o < 8; o <<= 1) {
                int n = __shfl_up_sync(0xffu, w, o);
                if (t >= o) w += n;
            }
            wsum[t] = w;
        }
        __syncthreads();
        int incl = v + (wid ? wsum[wid - 1] : 0);
        int excl = incl - c;
        int blockTotal = wsum[7];

        if (t == 0) {
            *(volatile unsigned long long*)&g_bpack[b] =
                ((unsigned long long)(unsigned)blockTotal << 32) | 1ull;
        }
        if (t < 32) {
            int sum = 0;
            for (int p = lane; p < b; p += 32) {
                unsigned long long pk;
                do {
                    pk = *(volatile unsigned long long*)&g_bpack[p];
                } while ((pk & 1ull) == 0ull);
                sum += (int)(pk >> 32);
            }
#pragma unroll
            for (int o = 16; o; o >>= 1) sum += __shfl_down_sync(0xffffffffu, sum, o);
            if (t == 0) s_off = sum;
        }
        __syncthreads();

        int base = s_off + excl;
        if (i < NN) {
            g_rowstart[i] = base;
            g_cursor[i]   = base;
        }
        if (i == NN - 1) g_rowstart[NN] = base + c;
    } else {
        int idx = (blockIdx.x - SCAN_BLOCKS) * 256 + t;
        int v = idx >> 4, lane = idx & 15;
        if (v >= NN) return;
        float dinv = rsqrtf((float)(g_cnt[v] + 1));
        if (lane == 0) g_dinv[v] = dinv;
        float4 a = x[(size_t)v * 32 + lane * 2];
        float4 b4 = x[(size_t)v * 32 + lane * 2 + 1];
        float f[8] = {a.x, a.y, a.z, a.w, b4.x, b4.y, b4.z, b4.w};
        g_h0h[(size_t)v * 16 + lane] = pack8(f, dinv);
    }
}

// ---------------- 3) scatter edges + restore zero-state ----------------
__global__ void __launch_bounds__(256) scatter_kernel(const void* __restrict__ ei) {
    int is64 = block_is64((const unsigned int*)ei);
    int i = blockIdx.x * blockDim.x + threadIdx.x;
    if (i < NN) g_cnt[i] = 0;
    if (i < SCAN_BLOCKS) g_bpack[i] = 0ull;
    if (i == 0) g_ticket = 0;
    if (i < NE) {
        int s = load_idx(ei, i, is64);
        int d = load_idx(ei, (long long)NE + i, is64);
        if ((unsigned)s < (unsigned)NN && (unsigned)d < (unsigned)NN) {
            int p = atomicAdd(&g_cursor[d], 1);
            g_src_sorted[p] = s;
        }
    }
}

// ---------------- 4) hop1: x_hat -> h1_hat ----------------
__global__ void __launch_bounds__(256) prop1_kernel() {
    int g = blockIdx.x * blockDim.x + threadIdx.x;
    int v = g >> 4, lane = g & 15;
    if (v >= NN) return;
    float d = g_dinv[v];
    float sc = d * d;
    float acc[8];
    unpack8(g_h0h[(size_t)v * 16 + lane], acc);
    gather_accum(g_h0h, lane, g_rowstart[v], g_rowstart[v + 1], acc);
    g_h1h[(size_t)v * 16 + lane] = pack8(acc, sc);
}

// ---------------- 5) fused hop2 + GEMM ----------------
// Phase 1: block gathers its 64 h2 rows (fp32) into smem A-tile.
// Phase 2: tf32 split-mma GEMM as before.
#define AS_STRIDE 132
#define WS_STRIDE 136
#define GEMM_SMEM_BYTES ((64 * AS_STRIDE + 128 * WS_STRIDE) * 4)

__device__ __forceinline__ void mma8(float c[4], const unsigned a[4], const unsigned b[2]) {
    asm volatile(
        "mma.sync.aligned.m16n8k8.row.col.f32.tf32.tf32.f32 "
        "{%0,%1,%2,%3}, {%4,%5,%6,%7}, {%8,%9}, {%0,%1,%2,%3};\n"
        : "+f"(c[0]), "+f"(c[1]), "+f"(c[2]), "+f"(c[3])
        : "r"(a[0]), "r"(a[1]), "r"(a[2]), "r"(a[3]), "r"(b[0]), "r"(b[1]));
}
__device__ __forceinline__ void split_tf32(float x, unsigned& hi, unsigned& lo) {
    unsigned h;
    asm("cvt.rna.tf32.f32 %0, %1;" : "=r"(h) : "f"(x));
    hi = h;
    lo = __float_as_uint(x - __uint_as_float(h));
}

__global__ void __launch_bounds__(256) gemm_kernel(const float4* __restrict__ Wm,
                                                   const float* __restrict__ bias,
                                                   float* __restrict__ out) {
    extern __shared__ float smem[];
    float* As = smem;                       // [64][AS_STRIDE]
    float* Ws = smem + 64 * AS_STRIDE;      // [128][WS_STRIDE]

    int tid = threadIdx.x;
    int row0 = blockIdx.x * 64;

    // W tile load (independent of gather)
#pragma unroll
    for (int j = 0; j < 16; j++) {
        int idx = tid + j * 256;
        int r = idx >> 5;
        int c4 = idx & 31;
        float4 w = __ldg(&Wm[idx]);
        *(float4*)&Ws[r * WS_STRIDE + c4 * 4] = w;
    }

    // Phase 1: gather h2 rows for this block's 64 nodes into As (fp32)
#pragma unroll
    for (int k = 0; k < 4; k++) {
        int item = tid + k * 256;          // 0..1023
        int r = item >> 4;                 // node-in-block 0..63
        int lane = item & 15;
        int v = row0 + r;
        float acc[8] = {0.f, 0.f, 0.f, 0.f, 0.f, 0.f, 0.f, 0.f};
        if (v < NN) {
            float sc = g_dinv[v];
            unpack8(g_h1h[(size_t)v * 16 + lane], acc);
            gather_accum(g_h1h, lane, g_rowstart[v], g_rowstart[v + 1], acc);
#pragma unroll
            for (int j = 0; j < 8; j++) acc[j] *= sc;
        }
        *(float4*)&As[r * AS_STRIDE + lane * 8]     = *(float4*)&acc[0];
        *(float4*)&As[r * AS_STRIDE + lane * 8 + 4] = *(float4*)&acc[4];
    }
    __syncthreads();

    // Phase 2: GEMM
    int warp = tid >> 5, lane = tid & 31;
    int mwarp = warp & 1, nwarp = warp >> 1;
    int m0 = mwarp * 32, n0 = nwarp * 32;
    int lr = lane >> 2, lc = lane & 3;

    float c[2][4][4];
#pragma unroll
    for (int mt = 0; mt < 2; mt++)
#pragma unroll
        for (int nt = 0; nt < 4; nt++)
#pragma unroll
            for (int i = 0; i < 4; i++) c[mt][nt][i] = 0.f;

    for (int k0 = 0; k0 < 128; k0 += 8) {
        unsigned ahi[2][4], alo[2][4];
#pragma unroll
        for (int mt = 0; mt < 2; mt++) {
            int mb = m0 + mt * 16;
            float a0 = As[(mb + lr) * AS_STRIDE + k0 + lc];
            float a1 = As[(mb + lr + 8) * AS_STRIDE + k0 + lc];
            float a2 = As[(mb + lr) * AS_STRIDE + k0 + lc + 4];
            float a3 = As[(mb + lr + 8) * AS_STRIDE + k0 + lc + 4];
            split_tf32(a0, ahi[mt][0], alo[mt][0]);
            split_tf32(a1, ahi[mt][1], alo[mt][1]);
            split_tf32(a2, ahi[mt][2], alo[mt][2]);
            split_tf32(a3, ahi[mt][3], alo[mt][3]);
        }
        unsigned bhi[4][2], blo[4][2];
#pragma unroll
        for (int nt = 0; nt < 4; nt++) {
            int nb = n0 + nt * 8;
            float b0 = Ws[(k0 + lc) * WS_STRIDE + nb + lr];
            float b1 = Ws[(k0 + lc + 4) * WS_STRIDE + nb + lr];
            split_tf32(b0, bhi[nt][0], blo[nt][0]);
            split_tf32(b1, bhi[nt][1], blo[nt][1]);
        }
#pragma unroll
        for (int mt = 0; mt < 2; mt++)
#pragma unroll
            for (int nt = 0; nt < 4; nt++) {
                mma8(c[mt][nt], ahi[mt], bhi[nt]);
                mma8(c[mt][nt], alo[mt], bhi[nt]);
                mma8(c[mt][nt], ahi[mt], blo[nt]);
            }
    }

#pragma unroll
    for (int mt = 0; mt < 2; mt++) {
#pragma unroll
        for (int nt = 0; nt < 4; nt++) {
            int colBase = n0 + nt * 8 + 2 * lc;
            float b0 = __ldg(&bias[colBase]);
            float b1 = __ldg(&bias[colBase + 1]);
            int r0 = row0 + m0 + mt * 16 + lr;
            int r1 = r0 + 8;
            if (r0 < NN) {
                float2 o = make_float2(c[mt][nt][0] + b0, c[mt][nt][1] + b1);
                *(float2*)&out[(size_t)r0 * DD + colBase] = o;
            }
            if (r1 < NN) {
                float2 o = make_float2(c[mt][nt][2] + b0, c[mt][nt][3] + b1);
                *(float2*)&out[(size_t)r1 * DD + colBase] = o;
            }
        }
    }
}

// ---------------- launch ----------------
extern "C" void kernel_launch(void* const* d_in, const int* in_sizes, int n_in,
                              void* d_out, int out_size) {
    const float* x   = (const float*)d_in[0];
    const void*  ei  = d_in[1];
    const float* Wm  = (const float*)d_in[2];
    const float* bia = (const float*)d_in[3];
    float*       out = (float*)d_out;

    static bool attr_done = false;
    if (!attr_done) {
        cudaFuncSetAttribute(gemm_kernel, cudaFuncAttributeMaxDynamicSharedMemorySize,
                             GEMM_SMEM_BYTES);
        attr_done = true;
    }

    hist_kernel<<<(NE + 255) / 256, 256>>>(ei);                               // 1
    scan_scale_kernel<<<SCAN_BLOCKS + SCALE_BLOCKS, 256>>>((const float4*)x); // 2
    scatter_kernel<<<(NE + 255) / 256, 256>>>(ei);                            // 3

    prop1_kernel<<<(NN * 16 + 255) / 256, 256>>>();                           // 4 (profiled)
    gemm_kernel<<<(NN + 63) / 64, 256, GEMM_SMEM_BYTES>>>((const float4*)Wm, bia, out); // 5
}

// round 10
// speedup vs baseline: 1.0720x; 1.0720x over previous
#include <cuda_runtime.h>
#include <cuda_fp16.h>
#include <cstdint>

#define NN 100000
#define NE 1600000
#define DD 128
#define SCAN_BLOCKS ((NN + 255) / 256)       // 391
#define SCALE_BLOCKS ((NN * 16 + 255) / 256) // 6250

// ---------------- scratch (zero-initialized at module load) ----------------
__device__ int   g_cnt[NN];
__device__ int   g_rowstart[NN + 1];
__device__ int   g_cursor[NN];
__device__ float g_dinv[NN];
__device__ int   g_src_sorted[NE];
__device__ unsigned long long g_bpack[SCAN_BLOCKS];
__device__ int   g_ticket;
__device__ uint4 g_h0h[(size_t)NN * 16];  // x_hat  fp16 (8 halves / uint4)
__device__ uint4 g_h1h[(size_t)NN * 16];  // h1_hat fp16
__device__ uint4 g_h2h[(size_t)NN * 16];  // h2     fp16

// ---------------- helpers ----------------
__device__ __forceinline__ void unpack8(uint4 u, float f[8]) {
    float2 a = __half22float2(*(__half2*)&u.x);
    float2 b = __half22float2(*(__half2*)&u.y);
    float2 c = __half22float2(*(__half2*)&u.z);
    float2 d = __half22float2(*(__half2*)&u.w);
    f[0] = a.x; f[1] = a.y; f[2] = b.x; f[3] = b.y;
    f[4] = c.x; f[5] = c.y; f[6] = d.x; f[7] = d.y;
}
__device__ __forceinline__ uint4 pack8(const float f[8], float s) {
    __half2 a = __floats2half2_rn(f[0] * s, f[1] * s);
    __half2 b = __floats2half2_rn(f[2] * s, f[3] * s);
    __half2 c = __floats2half2_rn(f[4] * s, f[5] * s);
    __half2 d = __floats2half2_rn(f[6] * s, f[7] * s);
    uint4 u;
    u.x = *(unsigned*)&a; u.y = *(unsigned*)&b;
    u.z = *(unsigned*)&c; u.w = *(unsigned*)&d;
    return u;
}
// 3-level fp16 tree sum of 8 rows, then fp32 accumulate (per component)
__device__ __forceinline__ __half2 tree8(unsigned a0, unsigned a1, unsigned a2, unsigned a3,
                                         unsigned a4, unsigned a5, unsigned a6, unsigned a7) {
    __half2 p0 = __hadd2(*(__half2*)&a0, *(__half2*)&a1);
    __half2 p1 = __hadd2(*(__half2*)&a2, *(__half2*)&a3);
    __half2 p2 = __hadd2(*(__half2*)&a4, *(__half2*)&a5);
    __half2 p3 = __hadd2(*(__half2*)&a6, *(__half2*)&a7);
    return __hadd2(__hadd2(p0, p1), __hadd2(p2, p3));
}
__device__ __forceinline__ void accum_oct(const uint4 u[8], float acc[8]) {
    __half2 ox = tree8(u[0].x, u[1].x, u[2].x, u[3].x, u[4].x, u[5].x, u[6].x, u[7].x);
    __half2 oy = tree8(u[0].y, u[1].y, u[2].y, u[3].y, u[4].y, u[5].y, u[6].y, u[7].y);
    __half2 oz = tree8(u[0].z, u[1].z, u[2].z, u[3].z, u[4].z, u[5].z, u[6].z, u[7].z);
    __half2 ow = tree8(u[0].w, u[1].w, u[2].w, u[3].w, u[4].w, u[5].w, u[6].w, u[7].w);
    float2 fx = __half22float2(ox);
    float2 fy = __half22float2(oy);
    float2 fz = __half22float2(oz);
    float2 fw = __half22float2(ow);
    acc[0] += fx.x; acc[1] += fx.y; acc[2] += fy.x; acc[3] += fy.y;
    acc[4] += fz.x; acc[5] += fz.y; acc[6] += fw.x; acc[7] += fw.y;
}
__device__ __forceinline__ void accum_pair(uint4 a, uint4 b, float acc[8]) {
    __half2 hx = __hadd2(*(__half2*)&a.x, *(__half2*)&b.x);
    __half2 hy = __hadd2(*(__half2*)&a.y, *(__half2*)&b.y);
    __half2 hz = __hadd2(*(__half2*)&a.z, *(__half2*)&b.z);
    __half2 hw = __hadd2(*(__half2*)&a.w, *(__half2*)&b.w);
    float2 fx = __half22float2(hx);
    float2 fy = __half22float2(hy);
    float2 fz = __half22float2(hz);
    float2 fw = __half22float2(hw);
    acc[0] += fx.x; acc[1] += fx.y; acc[2] += fy.x; acc[3] += fy.y;
    acc[4] += fz.x; acc[5] += fz.y; acc[6] += fw.x; acc[7] += fw.y;
}
__device__ __forceinline__ void accum_one(uint4 u, float acc[8]) {
    float f[8];
    unpack8(u, f);
#pragma unroll
    for (int j = 0; j < 8; j++) acc[j] += f[j];
}

// gather loop: acc += sum over edges [e,e1) of hin[src]
__device__ __forceinline__ void gather_accum(const uint4* __restrict__ hin,
                                             int lane, int e, int e1, float acc[8]) {
    for (; e + 8 <= e1; e += 8) {
        int s[8];
#pragma unroll
        for (int k = 0; k < 8; k++) s[k] = __ldg(&g_src_sorted[e + k]);
        uint4 u[8];
#pragma unroll
        for (int k = 0; k < 8; k++) u[k] = __ldg(&hin[(size_t)s[k] * 16 + lane]);
        accum_oct(u, acc);
    }
    for (; e + 2 <= e1; e += 2) {
        int s0 = __ldg(&g_src_sorted[e]);
        int s1 = __ldg(&g_src_sorted[e + 1]);
        uint4 u0 = __ldg(&hin[(size_t)s0 * 16 + lane]);
        uint4 u1 = __ldg(&hin[(size_t)s1 * 16 + lane]);
        accum_pair(u0, u1, acc);
    }
    if (e < e1) {
        int s = __ldg(&g_src_sorted[e]);
        accum_one(__ldg(&hin[(size_t)s * 16 + lane]), acc);
    }
}

// block-local dtype detect: int64 little-endian => all odd 32-bit words zero
__device__ __forceinline__ int block_is64(const unsigned int* e) {
    unsigned m = 0;
    int t = threadIdx.x;
    for (int k = t; k < 1024; k += 256) m |= e[2 * k + 1];
    return __syncthreads_or((int)m) == 0;
}
__device__ __forceinline__ int load_idx(const void* ei, long long pos, int is64) {
    if (is64) return (int)((const long long*)ei)[pos];
    return ((const int*)ei)[pos];
}

// ---------------- 1) histogram of dst ----------------
__global__ void __launch_bounds__(256) hist_kernel(const void* __restrict__ ei) {
    int is64 = block_is64((const unsigned int*)ei);
    int i = blockIdx.x * blockDim.x + threadIdx.x;
    if (i < NE) {
        int d = load_idx(ei, (long long)NE + i, is64);
        if ((unsigned)d < (unsigned)NN) atomicAdd(&g_cnt[d], 1);
    }
}

// ---------------- 2) fused: decoupled-lookback scan | x prescale ----------
__global__ void __launch_bounds__(256) scan_scale_kernel(const float4* __restrict__ x) {
    int t = threadIdx.x;
    if (blockIdx.x < SCAN_BLOCKS) {
        __shared__ int s_b;
        __shared__ int wsum[8];
        __shared__ int s_off;
        if (t == 0) s_b = atomicAdd(&g_ticket, 1);
        __syncthreads();
        int b = s_b;
        int lane = t & 31, wid = t >> 5;
        int i = b * 256 + t;

        int c = (i < NN) ? g_cnt[i] : 0;
        int v = c;
#pragma unroll
        for (int o = 1; o < 32; o <<= 1) {
            int n = __shfl_up_sync(0xffffffffu, v, o);
            if (lane >= o) v += n;
        }
        if (lane == 31) wsum[wid] = v;
        __syncthreads();
        if (t < 8) {
            int w = wsum[t];
#pragma unroll
            for (int o = 1; o < 8; o <<= 1) {
                int n = __shfl_up_sync(0xffu, w, o);
                if (t >= o) w += n;
            }
            wsum[t] = w;
        }
        __syncthreads();
        int incl = v + (wid ? wsum[wid - 1] : 0);
        int excl = incl - c;
        int blockTotal = wsum[7];

        if (t == 0) {
            *(volatile unsigned long long*)&g_bpack[b] =
                ((unsigned long long)(unsigned)blockTotal << 32) | 1ull;
        }
        if (t < 32) {
            int sum = 0;
            for (int p = lane; p < b; p += 32) {
                unsigned long long pk;
                do {
                    pk = *(volatile unsigned long long*)&g_bpack[p];
                } while ((pk & 1ull) == 0ull);
                sum += (int)(pk >> 32);
            }
#pragma unroll
            for (int o = 16; o; o >>= 1) sum += __shfl_down_sync(0xffffffffu, sum, o);
            if (t == 0) s_off = sum;
        }
        __syncthreads();

        int base = s_off + excl;
        if (i < NN) {
            g_rowstart[i] = base;
            g_cursor[i]   = base;
        }
        if (i == NN - 1) g_rowstart[NN] = base + c;
    } else {
        int idx = (blockIdx.x - SCAN_BLOCKS) * 256 + t;
        int v = idx >> 4, lane = idx & 15;
        if (v >= NN) return;
        float dinv = rsqrtf((float)(g_cnt[v] + 1));
        if (lane == 0) g_dinv[v] = dinv;
        float4 a = x[(size_t)v * 32 + lane * 2];
        float4 b4 = x[(size_t)v * 32 + lane * 2 + 1];
        float f[8] = {a.x, a.y, a.z, a.w, b4.x, b4.y, b4.z, b4.w};
        g_h0h[(size_t)v * 16 + lane] = pack8(f, dinv);
    }
}

// ---------------- 3) scatter edges + restore zero-state ----------------
__global__ void __launch_bounds__(256) scatter_kernel(const void* __restrict__ ei) {
    int is64 = block_is64((const unsigned int*)ei);
    int i = blockIdx.x * blockDim.x + threadIdx.x;
    if (i < NN) g_cnt[i] = 0;
    if (i < SCAN_BLOCKS) g_bpack[i] = 0ull;
    if (i == 0) g_ticket = 0;
    if (i < NE) {
        int s = load_idx(ei, i, is64);
        int d = load_idx(ei, (long long)NE + i, is64);
        if ((unsigned)s < (unsigned)NN && (unsigned)d < (unsigned)NN) {
            int p = atomicAdd(&g_cursor[d], 1);
            g_src_sorted[p] = s;
        }
    }
}

// ---------------- 4) hop1: x_hat -> h1_hat ----------------
__global__ void __launch_bounds__(256) prop1_kernel() {
    int g = blockIdx.x * blockDim.x + threadIdx.x;
    int v = g >> 4, lane = g & 15;
    if (v >= NN) return;
    float d = g_dinv[v];
    float sc = d * d;
    float acc[8];
    unpack8(g_h0h[(size_t)v * 16 + lane], acc);
    gather_accum(g_h0h, lane, g_rowstart[v], g_rowstart[v + 1], acc);
    g_h1h[(size_t)v * 16 + lane] = pack8(acc, sc);
}

// ---------------- 5) hop2: h1_hat -> h2 (fp16) ----------------
__global__ void __launch_bounds__(256) prop2_kernel() {
    int g = blockIdx.x * blockDim.x + threadIdx.x;
    int v = g >> 4, lane = g & 15;
    if (v >= NN) return;
    float sc = g_dinv[v];
    float acc[8];
    unpack8(g_h1h[(size_t)v * 16 + lane], acc);
    gather_accum(g_h1h, lane, g_rowstart[v], g_rowstart[v + 1], acc);
    g_h2h[(size_t)v * 16 + lane] = pack8(acc, sc);
}

// ---------------- 6) GEMM via tf32 mma with 3-term split (A in fp16) -------
#define AS_STRIDE 132
#define WS_STRIDE 136
#define GEMM_SMEM_BYTES ((64 * AS_STRIDE + 128 * WS_STRIDE) * 4)

__device__ __forceinline__ void mma8(float c[4], const unsigned a[4], const unsigned b[2]) {
    asm volatile(
        "mma.sync.aligned.m16n8k8.row.col.f32.tf32.tf32.f32 "
        "{%0,%1,%2,%3}, {%4,%5,%6,%7}, {%8,%9}, {%0,%1,%2,%3};\n"
        : "+f"(c[0]), "+f"(c[1]), "+f"(c[2]), "+f"(c[3])
        : "r"(a[0]), "r"(a[1]), "r"(a[2]), "r"(a[3]), "r"(b[0]), "r"(b[1]));
}
__device__ __forceinline__ void split_tf32(float x, unsigned& hi, unsigned& lo) {
    unsigned h;
    asm("cvt.rna.tf32.f32 %0, %1;" : "=r"(h) : "f"(x));
    hi = h;
    lo = __float_as_uint(x - __uint_as_float(h));
}

__global__ void __launch_bounds__(256) gemm_kernel(const float4* __restrict__ Wm,
                                                   const float* __restrict__ bias,
                                                   float* __restrict__ out) {
    extern __shared__ float smem[];
    float* As = smem;                       // [64][AS_STRIDE]
    float* Ws = smem + 64 * AS_STRIDE;      // [128][WS_STRIDE]

    int tid = threadIdx.x;
    int row0 = blockIdx.x * 64;

#pragma unroll
    for (int j = 0; j < 16; j++) {
        int idx = tid + j * 256;
        int r = idx >> 5;
        int c4 = idx & 31;
        float4 w = __ldg(&Wm[idx]);
        *(float4*)&Ws[r * WS_STRIDE + c4 * 4] = w;
    }
    const uint2* A2 = (const uint2*)g_h2h;
#pragma unroll
    for (int j = 0; j < 8; j++) {
        int idx = tid + j * 256;
        int r = idx >> 5;
        int c4 = idx & 31;
        int gr = row0 + r;
        uint2 u = (gr < NN) ? __ldg(&A2[(size_t)gr * 32 + c4]) : make_uint2(0u, 0u);
        float2 f0 = __half22float2(*(__half2*)&u.x);
        float2 f1 = __half22float2(*(__half2*)&u.y);
        float4 a = make_float4(f0.x, f0.y, f1.x, f1.y);
        *(float4*)&As[r * AS_STRIDE + c4 * 4] = a;
    }
    __syncthreads();

    int warp = tid >> 5, lane = tid & 31;
    int mwarp = warp & 1, nwarp = warp >> 1;
    int m0 = mwarp * 32, n0 = nwarp * 32;
    int lr = lane >> 2, lc = lane & 3;

    float c[2][4][4];
#pragma unroll
    for (int mt = 0; mt < 2; mt++)
#pragma unroll
        for (int nt = 0; nt < 4; nt++)
#pragma unroll
            for (int i = 0; i < 4; i++) c[mt][nt][i] = 0.f;

    for (int k0 = 0; k0 < 128; k0 += 8) {
        unsigned ahi[2][4], alo[2][4];
#pragma unroll
        for (int mt = 0; mt < 2; mt++) {
            int mb = m0 + mt * 16;
            float a0 = As[(mb + lr) * AS_STRIDE + k0 + lc];
            float a1 = As[(mb + lr + 8) * AS_STRIDE + k0 + lc];
            float a2 = As[(mb + lr) * AS_STRIDE + k0 + lc + 4];
            float a3 = As[(mb + lr + 8) * AS_STRIDE + k0 + lc + 4];
            split_tf32(a0, ahi[mt][0], alo[mt][0]);
            split_tf32(a1, ahi[mt][1], alo[mt][1]);
            split_tf32(a2, ahi[mt][2], alo[mt][2]);
            split_tf32(a3, ahi[mt][3], alo[mt][3]);
        }
        unsigned bhi[4][2], blo[4][2];
#pragma unroll
        for (int nt = 0; nt < 4; nt++) {
            int nb = n0 + nt * 8;
            float b0 = Ws[(k0 + lc) * WS_STRIDE + nb + lr];
            float b1 = Ws[(k0 + lc + 4) * WS_STRIDE + nb + lr];
            split_tf32(b0, bhi[nt][0], blo[nt][0]);
            split_tf32(b1, bhi[nt][1], blo[nt][1]);
        }
#pragma unroll
        for (int mt = 0; mt < 2; mt++)
#pragma unroll
            for (int nt = 0; nt < 4; nt++) {
                mma8(c[mt][nt], ahi[mt], bhi[nt]);
                mma8(c[mt][nt], alo[mt], bhi[nt]);
                mma8(c[mt][nt], ahi[mt], blo[nt]);
            }
    }

#pragma unroll
    for (int mt = 0; mt < 2; mt++) {
#pragma unroll
        for (int nt = 0; nt < 4; nt++) {
            int colBase = n0 + nt * 8 + 2 * lc;
            float b0 = __ldg(&bias[colBase]);
            float b1 = __ldg(&bias[colBase + 1]);
            int r0 = row0 + m0 + mt * 16 + lr;
            int r1 = r0 + 8;
            if (r0 < NN) {
                float2 o = make_float2(c[mt][nt][0] + b0, c[mt][nt][1] + b1);
                *(float2*)&out[(size_t)r0 * DD + colBase] = o;
            }
            if (r1 < NN) {
                float2 o = make_float2(c[mt][nt][2] + b0, c[mt][nt][3] + b1);
                *(float2*)&out[(size_t)r1 * DD + colBase] = o;
            }
        }
    }
}

// ---------------- launch ----------------
extern "C" void kernel_launch(void* const* d_in, const int* in_sizes, int n_in,
                              void* d_out, int out_size) {
    const float* x   = (const float*)d_in[0];
    const void*  ei  = d_in[1];
    const float* Wm  = (const float*)d_in[2];
    const float* bia = (const float*)d_in[3];
    float*       out = (float*)d_out;

    static bool attr_done = false;
    if (!attr_done) {
        cudaFuncSetAttribute(gemm_kernel, cudaFuncAttributeMaxDynamicSharedMemorySize,
                             GEMM_SMEM_BYTES);
        attr_done = true;
    }

    hist_kernel<<<(NE + 255) / 256, 256>>>(ei);                               // 1
    scan_scale_kernel<<<SCAN_BLOCKS + SCALE_BLOCKS, 256>>>((const float4*)x); // 2
    scatter_kernel<<<(NE + 255) / 256, 256>>>(ei);                            // 3

    int prop_blocks = (NN * 16 + 255) / 256;
    prop1_kernel<<<prop_blocks, 256>>>();                                     // 4 (profiled)
    prop2_kernel<<<prop_blocks, 256>>>();                                     // 5
    gemm_kernel<<<(NN + 63) / 64, 256, GEMM_SMEM_BYTES>>>((const float4*)Wm, bia, out); // 6
}

// round 11
// speedup vs baseline: 1.1124x; 1.0378x over previous
#include <cuda_runtime.h>
#include <cuda_fp16.h>
#include <cstdint>

#define NN 100000
#define NE 1600000
#define DD 128
#define SCAN_BLOCKS ((NN + 255) / 256)       // 391
#define SCALE_BLOCKS ((NN * 16 + 255) / 256) // 6250

// ---------------- scratch (zero-initialized at module load) ----------------
__device__ int   g_cnt[NN];
__device__ int   g_rowstart[NN + 1];
__device__ int   g_cursor[NN];
__device__ float g_dinv[NN];
__device__ int   g_src_sorted[NE];
__device__ unsigned long long g_bpack[SCAN_BLOCKS];
__device__ int   g_ticket;
__device__ uint4 g_h0h[(size_t)NN * 16];  // x_hat  fp16 (8 halves / uint4)
__device__ uint4 g_h1h[(size_t)NN * 16];  // h1_hat fp16
__device__ uint4 g_h2h[(size_t)NN * 16];  // h2     fp16

// ---------------- helpers ----------------
__device__ __forceinline__ void unpack8(uint4 u, float f[8]) {
    float2 a = __half22float2(*(__half2*)&u.x);
    float2 b = __half22float2(*(__half2*)&u.y);
    float2 c = __half22float2(*(__half2*)&u.z);
    float2 d = __half22float2(*(__half2*)&u.w);
    f[0] = a.x; f[1] = a.y; f[2] = b.x; f[3] = b.y;
    f[4] = c.x; f[5] = c.y; f[6] = d.x; f[7] = d.y;
}
__device__ __forceinline__ uint4 pack8(const float f[8], float s) {
    __half2 a = __floats2half2_rn(f[0] * s, f[1] * s);
    __half2 b = __floats2half2_rn(f[2] * s, f[3] * s);
    __half2 c = __floats2half2_rn(f[4] * s, f[5] * s);
    __half2 d = __floats2half2_rn(f[6] * s, f[7] * s);
    uint4 u;
    u.x = *(unsigned*)&a; u.y = *(unsigned*)&b;
    u.z = *(unsigned*)&c; u.w = *(unsigned*)&d;
    return u;
}
// add fp16-pairwise sum of (a,b) into fp32 acc
__device__ __forceinline__ void accum_pair(uint4 a, uint4 b, float acc[8]) {
    __half2 hx = __hadd2(*(__half2*)&a.x, *(__half2*)&b.x);
    __half2 hy = __hadd2(*(__half2*)&a.y, *(__half2*)&b.y);
    __half2 hz = __hadd2(*(__half2*)&a.z, *(__half2*)&b.z);
    __half2 hw = __hadd2(*(__half2*)&a.w, *(__half2*)&b.w);
    float2 fx = __half22float2(hx);
    float2 fy = __half22float2(hy);
    float2 fz = __half22float2(hz);
    float2 fw = __half22float2(hw);
    acc[0] += fx.x; acc[1] += fx.y; acc[2] += fy.x; acc[3] += fy.y;
    acc[4] += fz.x; acc[5] += fz.y; acc[6] += fw.x; acc[7] += fw.y;
}
__device__ __forceinline__ void accum_one(uint4 u, float acc[8]) {
    float f[8];
    unpack8(u, f);
#pragma unroll
    for (int j = 0; j < 8; j++) acc[j] += f[j];
}

// gather loop: acc += sum over edges [e,e1) of hin[src]
__device__ __forceinline__ void gather_accum(const uint4* __restrict__ hin,
                                             int lane, int e, int e1, float acc[8]) {
    for (; e + 8 <= e1; e += 8) {
        int s[8];
#pragma unroll
        for (int k = 0; k < 8; k++) s[k] = __ldg(&g_src_sorted[e + k]);
        uint4 u[8];
#pragma unroll
        for (int k = 0; k < 8; k++) u[k] = __ldg(&hin[(size_t)s[k] * 16 + lane]);
#pragma unroll
        for (int p = 0; p < 4; p++) accum_pair(u[2 * p], u[2 * p + 1], acc);
    }
    for (; e + 2 <= e1; e += 2) {
        int s0 = __ldg(&g_src_sorted[e]);
        int s1 = __ldg(&g_src_sorted[e + 1]);
        uint4 u0 = __ldg(&hin[(size_t)s0 * 16 + lane]);
        uint4 u1 = __ldg(&hin[(size_t)s1 * 16 + lane]);
        accum_pair(u0, u1, acc);
    }
    if (e < e1) {
        int s = __ldg(&g_src_sorted[e]);
        accum_one(__ldg(&hin[(size_t)s * 16 + lane]), acc);
    }
}

// block-local dtype detect: int64 little-endian => all odd 32-bit words zero
__device__ __forceinline__ int block_is64(const unsigned int* e) {
    unsigned m = 0;
    int t = threadIdx.x;
    for (int k = t; k < 1024; k += 256) m |= e[2 * k + 1];
    return __syncthreads_or((int)m) == 0;
}
__device__ __forceinline__ int load_idx(const void* ei, long long pos, int is64) {
    if (is64) return (int)((const long long*)ei)[pos];
    return ((const int*)ei)[pos];
}

// ---------------- 1) histogram of dst ----------------
__global__ void __launch_bounds__(256) hist_kernel(const void* __restrict__ ei) {
    int is64 = block_is64((const unsigned int*)ei);
    int i = blockIdx.x * blockDim.x + threadIdx.x;
    if (i < NE) {
        int d = load_idx(ei, (long long)NE + i, is64);
        if ((unsigned)d < (unsigned)NN) atomicAdd(&g_cnt[d], 1);
    }
}

// ---------------- 2) decoupled-lookback scan ----------------
__global__ void __launch_bounds__(256) scan_kernel() {
    __shared__ int s_b;
    __shared__ int wsum[8];
    __shared__ int s_off;
    int t = threadIdx.x;
    if (t == 0) s_b = atomicAdd(&g_ticket, 1);
    __syncthreads();
    int b = s_b;
    int lane = t & 31, wid = t >> 5;
    int i = b * 256 + t;

    int c = (i < NN) ? g_cnt[i] : 0;
    int v = c;
#pragma unroll
    for (int o = 1; o < 32; o <<= 1) {
        int n = __shfl_up_sync(0xffffffffu, v, o);
        if (lane >= o) v += n;
    }
    if (lane == 31) wsum[wid] = v;
    __syncthreads();
    if (t < 8) {
        int w = wsum[t];
#pragma unroll
        for (int o = 1; o < 8; o <<= 1) {
            int n = __shfl_up_sync(0xffu, w, o);
            if (t >= o) w += n;
        }
        wsum[t] = w;
    }
    __syncthreads();
    int incl = v + (wid ? wsum[wid - 1] : 0);
    int excl = incl - c;
    int blockTotal = wsum[7];

    if (t == 0) {
        *(volatile unsigned long long*)&g_bpack[b] =
            ((unsigned long long)(unsigned)blockTotal << 32) | 1ull;
    }
    if (t < 32) {
        int sum = 0;
        for (int p = lane; p < b; p += 32) {
            unsigned long long pk;
            do {
                pk = *(volatile unsigned long long*)&g_bpack[p];
            } while ((pk & 1ull) == 0ull);
            sum += (int)(pk >> 32);
        }
#pragma unroll
        for (int o = 16; o; o >>= 1) sum += __shfl_down_sync(0xffffffffu, sum, o);
        if (t == 0) s_off = sum;
    }
    __syncthreads();

    int base = s_off + excl;
    if (i < NN) {
        g_rowstart[i] = base;
        g_cursor[i]   = base;
    }
    if (i == NN - 1) g_rowstart[NN] = base + c;
}

// ---------------- 3) x prescale: x_hat = dinv*x (fp16) ----------------
__global__ void __launch_bounds__(256) scale_kernel(const float4* __restrict__ x) {
    int idx = blockIdx.x * blockDim.x + threadIdx.x;
    int v = idx >> 4, lane = idx & 15;
    if (v >= NN) return;
    float dinv = rsqrtf((float)(g_cnt[v] + 1));
    if (lane == 0) g_dinv[v] = dinv;
    float4 a = x[(size_t)v * 32 + lane * 2];
    float4 b4 = x[(size_t)v * 32 + lane * 2 + 1];
    float f[8] = {a.x, a.y, a.z, a.w, b4.x, b4.y, b4.z, b4.w};
    g_h0h[(size_t)v * 16 + lane] = pack8(f, dinv);
}

// ---------------- 4) scatter edges + restore zero-state (profiled) --------
__global__ void __launch_bounds__(256) scatter_kernel(const void* __restrict__ ei) {
    int is64 = block_is64((const unsigned int*)ei);
    int i = blockIdx.x * blockDim.x + threadIdx.x;
    if (i < NN) g_cnt[i] = 0;
    if (i < SCAN_BLOCKS) g_bpack[i] = 0ull;
    if (i == 0) g_ticket = 0;
    if (i < NE) {
        int s = load_idx(ei, i, is64);
        int d = load_idx(ei, (long long)NE + i, is64);
        if ((unsigned)s < (unsigned)NN && (unsigned)d < (unsigned)NN) {
            int p = atomicAdd(&g_cursor[d], 1);
            g_src_sorted[p] = s;
        }
    }
}

// ---------------- 5) hop1: x_hat -> h1_hat ----------------
__global__ void __launch_bounds__(256) prop1_kernel() {
    int g = blockIdx.x * blockDim.x + threadIdx.x;
    int v = g >> 4, lane = g & 15;
    if (v >= NN) return;
    float d = g_dinv[v];
    float sc = d * d;
    float acc[8];
    unpack8(g_h0h[(size_t)v * 16 + lane], acc);
    gather_accum(g_h0h, lane, g_rowstart[v], g_rowstart[v + 1], acc);
    g_h1h[(size_t)v * 16 + lane] = pack8(acc, sc);
}

// ---------------- 6) hop2: h1_hat -> h2 (fp16) ----------------
__global__ void __launch_bounds__(256) prop2_kernel() {
    int g = blockIdx.x * blockDim.x + threadIdx.x;
    int v = g >> 4, lane = g & 15;
    if (v >= NN) return;
    float sc = g_dinv[v];
    float acc[8];
    unpack8(g_h1h[(size_t)v * 16 + lane], acc);
    gather_accum(g_h1h, lane, g_rowstart[v], g_rowstart[v + 1], acc);
    g_h2h[(size_t)v * 16 + lane] = pack8(acc, sc);
}

// ---------------- 7) GEMM: tf32 mma, A exact (from fp16) -> 2 mmas --------
#define AS_STRIDE 132
#define WS_STRIDE 136
#define GEMM_SMEM_BYTES ((64 * AS_STRIDE + 128 * WS_STRIDE) * 4)

__device__ __forceinline__ void mma8(float c[4], const unsigned a[4], const unsigned b[2]) {
    asm volatile(
        "mma.sync.aligned.m16n8k8.row.col.f32.tf32.tf32.f32 "
        "{%0,%1,%2,%3}, {%4,%5,%6,%7}, {%8,%9}, {%0,%1,%2,%3};\n"
        : "+f"(c[0]), "+f"(c[1]), "+f"(c[2]), "+f"(c[3])
        : "r"(a[0]), "r"(a[1]), "r"(a[2]), "r"(a[3]), "r"(b[0]), "r"(b[1]));
}
__device__ __forceinline__ unsigned to_tf32(float x) {
    unsigned h;
    asm("cvt.rna.tf32.f32 %0, %1;" : "=r"(h) : "f"(x));
    return h;
}
__device__ __forceinline__ void split_tf32(float x, unsigned& hi, unsigned& lo) {
    unsigned h = to_tf32(x);
    hi = h;
    lo = __float_as_uint(x - __uint_as_float(h));
}

__global__ void __launch_bounds__(256) gemm_kernel(const float4* __restrict__ Wm,
                                                   const float* __restrict__ bias,
                                                   float* __restrict__ out) {
    extern __shared__ float smem[];
    float* As = smem;                       // [64][AS_STRIDE]
    float* Ws = smem + 64 * AS_STRIDE;      // [128][WS_STRIDE]

    int tid = threadIdx.x;
    int row0 = blockIdx.x * 64;

#pragma unroll
    for (int j = 0; j < 16; j++) {
        int idx = tid + j * 256;
        int r = idx >> 5;
        int c4 = idx & 31;
        float4 w = __ldg(&Wm[idx]);
        *(float4*)&Ws[r * WS_STRIDE + c4 * 4] = w;
    }
    const uint2* A2 = (const uint2*)g_h2h;
#pragma unroll
    for (int j = 0; j < 8; j++) {
        int idx = tid + j * 256;
        int r = idx >> 5;
        int c4 = idx & 31;
        int gr = row0 + r;
        uint2 u = (gr < NN) ? __ldg(&A2[(size_t)gr * 32 + c4]) : make_uint2(0u, 0u);
        float2 f0 = __half22float2(*(__half2*)&u.x);
        float2 f1 = __half22float2(*(__half2*)&u.y);
        float4 a = make_float4(f0.x, f0.y, f1.x, f1.y);
        *(float4*)&As[r * AS_STRIDE + c4 * 4] = a;
    }
    __syncthreads();

    int warp = tid >> 5, lane = tid & 31;
    int mwarp = warp & 1, nwarp = warp >> 1;
    int m0 = mwarp * 32, n0 = nwarp * 32;
    int lr = lane >> 2, lc = lane & 3;

    float c[2][4][4];
#pragma unroll
    for (int mt = 0; mt < 2; mt++)
#pragma unroll
        for (int nt = 0; nt < 4; nt++)
#pragma unroll
            for (int i = 0; i < 4; i++) c[mt][nt][i] = 0.f;

    for (int k0 = 0; k0 < 128; k0 += 8) {
        // A is exact in tf32 (values originate from fp16): hi-only
        unsigned ahi[2][4];
#pragma unroll
        for (int mt = 0; mt < 2; mt++) {
            int mb = m0 + mt * 16;
            ahi[mt][0] = to_tf32(As[(mb + lr) * AS_STRIDE + k0 + lc]);
            ahi[mt][1] = to_tf32(As[(mb + lr + 8) * AS_STRIDE + k0 + lc]);
            ahi[mt][2] = to_tf32(As[(mb + lr) * AS_STRIDE + k0 + lc + 4]);
            ahi[mt][3] = to_tf32(As[(mb + lr + 8) * AS_STRIDE + k0 + lc + 4]);
        }
        unsigned bhi[4][2], blo[4][2];
#pragma unroll
        for (int nt = 0; nt < 4; nt++) {
            int nb = n0 + nt * 8;
            float b0 = Ws[(k0 + lc) * WS_STRIDE + nb + lr];
            float b1 = Ws[(k0 + lc + 4) * WS_STRIDE + nb + lr];
            split_tf32(b0, bhi[nt][0], blo[nt][0]);
            split_tf32(b1, bhi[nt][1], blo[nt][1]);
        }
#pragma unroll
        for (int mt = 0; mt < 2; mt++)
#pragma unroll
            for (int nt = 0; nt < 4; nt++) {
                mma8(c[mt][nt], ahi[mt], bhi[nt]);
                mma8(c[mt][nt], ahi[mt], blo[nt]);
            }
    }

#pragma unroll
    for (int mt = 0; mt < 2; mt++) {
#pragma unroll
        for (int nt = 0; nt < 4; nt++) {
            int colBase = n0 + nt * 8 + 2 * lc;
            float b0 = __ldg(&bias[colBase]);
            float b1 = __ldg(&bias[colBase + 1]);
            int r0 = row0 + m0 + mt * 16 + lr;
            int r1 = r0 + 8;
            if (r0 < NN) {
                float2 o = make_float2(c[mt][nt][0] + b0, c[mt][nt][1] + b1);
                *(float2*)&out[(size_t)r0 * DD + colBase] = o;
            }
            if (r1 < NN) {
                float2 o = make_float2(c[mt][nt][2] + b0, c[mt][nt][3] + b1);
                *(float2*)&out[(size_t)r1 * DD + colBase] = o;
            }
        }
    }
}

// ---------------- launch ----------------
extern "C" void kernel_launch(void* const* d_in, const int* in_sizes, int n_in,
                              void* d_out, int out_size) {
    const float* x   = (const float*)d_in[0];
    const void*  ei  = d_in[1];
    const float* Wm  = (const float*)d_in[2];
    const float* bia = (const float*)d_in[3];
    float*       out = (float*)d_out;

    static bool attr_done = false;
    if (!attr_done) {
        cudaFuncSetAttribute(gemm_kernel, cudaFuncAttributeMaxDynamicSharedMemorySize,
                             GEMM_SMEM_BYTES);
        attr_done = true;
    }

    hist_kernel<<<(NE + 255) / 256, 256>>>(ei);                        // 1
    scan_kernel<<<SCAN_BLOCKS, 256>>>();                               // 2
    scale_kernel<<<SCALE_BLOCKS, 256>>>((const float4*)x);             // 3
    scatter_kernel<<<(NE + 255) / 256, 256>>>(ei);                     // 4 (profiled)

    int prop_blocks = (NN * 16 + 255) / 256;
    prop1_kernel<<<prop_blocks, 256>>>();                              // 5
    prop2_kernel<<<prop_blocks, 256>>>();                              // 6
    gemm_kernel<<<(NN + 63) / 64, 256, GEMM_SMEM_BYTES>>>((const float4*)Wm, bia, out); // 7
}

// round 12
// speedup vs baseline: 1.1345x; 1.0198x over previous
#include <cuda_runtime.h>
#include <cuda_fp16.h>
#include <cstdint>

#define NN 100000
#define NE 1600000
#define DD 128
#define SCAN_BLOCKS ((NN + 255) / 256)        // 391
#define EDGE_BLOCKS ((NE + 255) / 256)        // 6250
#define SCALE_BLOCKS ((NN * 16 + 255) / 256)  // 6250

// ---------------- scratch (zero-initialized at module load) ----------------
__device__ int   g_is64;
__device__ int   g_cnt[NN];
__device__ int   g_rowstart[NN + 1];
__device__ int   g_cursor[NN];
__device__ float g_dinv[NN];
__device__ int   g_src_sorted[NE];
__device__ unsigned long long g_bpack[SCAN_BLOCKS];
__device__ int   g_ticket;
__device__ uint4 g_h0h[(size_t)NN * 16];  // x_hat  fp16 (8 halves / uint4)
__device__ uint4 g_h1h[(size_t)NN * 16];  // h1_hat fp16
__device__ uint4 g_h2h[(size_t)NN * 16];  // h2     fp16

// ---------------- helpers ----------------
__device__ __forceinline__ void unpack8(uint4 u, float f[8]) {
    float2 a = __half22float2(*(__half2*)&u.x);
    float2 b = __half22float2(*(__half2*)&u.y);
    float2 c = __half22float2(*(__half2*)&u.z);
    float2 d = __half22float2(*(__half2*)&u.w);
    f[0] = a.x; f[1] = a.y; f[2] = b.x; f[3] = b.y;
    f[4] = c.x; f[5] = c.y; f[6] = d.x; f[7] = d.y;
}
__device__ __forceinline__ uint4 pack8(const float f[8], float s) {
    __half2 a = __floats2half2_rn(f[0] * s, f[1] * s);
    __half2 b = __floats2half2_rn(f[2] * s, f[3] * s);
    __half2 c = __floats2half2_rn(f[4] * s, f[5] * s);
    __half2 d = __floats2half2_rn(f[6] * s, f[7] * s);
    uint4 u;
    u.x = *(unsigned*)&a; u.y = *(unsigned*)&b;
    u.z = *(unsigned*)&c; u.w = *(unsigned*)&d;
    return u;
}
__device__ __forceinline__ void accum_pair(uint4 a, uint4 b, float acc[8]) {
    __half2 hx = __hadd2(*(__half2*)&a.x, *(__half2*)&b.x);
    __half2 hy = __hadd2(*(__half2*)&a.y, *(__half2*)&b.y);
    __half2 hz = __hadd2(*(__half2*)&a.z, *(__half2*)&b.z);
    __half2 hw = __hadd2(*(__half2*)&a.w, *(__half2*)&b.w);
    float2 fx = __half22float2(hx);
    float2 fy = __half22float2(hy);
    float2 fz = __half22float2(hz);
    float2 fw = __half22float2(hw);
    acc[0] += fx.x; acc[1] += fx.y; acc[2] += fy.x; acc[3] += fy.y;
    acc[4] += fz.x; acc[5] += fz.y; acc[6] += fw.x; acc[7] += fw.y;
}
__device__ __forceinline__ void accum_one(uint4 u, float acc[8]) {
    float f[8];
    unpack8(u, f);
#pragma unroll
    for (int j = 0; j < 8; j++) acc[j] += f[j];
}

__device__ __forceinline__ void gather_accum(const uint4* __restrict__ hin,
                                             int lane, int e, int e1, float acc[8]) {
    for (; e + 8 <= e1; e += 8) {
        int s[8];
#pragma unroll
        for (int k = 0; k < 8; k++) s[k] = __ldg(&g_src_sorted[e + k]);
        uint4 u[8];
#pragma unroll
        for (int k = 0; k < 8; k++) u[k] = __ldg(&hin[(size_t)s[k] * 16 + lane]);
#pragma unroll
        for (int p = 0; p < 4; p++) accum_pair(u[2 * p], u[2 * p + 1], acc);
    }
    for (; e + 2 <= e1; e += 2) {
        int s0 = __ldg(&g_src_sorted[e]);
        int s1 = __ldg(&g_src_sorted[e + 1]);
        uint4 u0 = __ldg(&hin[(size_t)s0 * 16 + lane]);
        uint4 u1 = __ldg(&hin[(size_t)s1 * 16 + lane]);
        accum_pair(u0, u1, acc);
    }
    if (e < e1) {
        int s = __ldg(&g_src_sorted[e]);
        accum_one(__ldg(&hin[(size_t)s * 16 + lane]), acc);
    }
}

__device__ __forceinline__ int load_idx(const void* ei, long long pos, int is64) {
    if (is64) return (int)((const long long*)ei)[pos];
    return ((const int*)ei)[pos];
}

// ---------------- 1) dtype detect (tiny) ----------------
__global__ void detect_kernel(const unsigned int* __restrict__ e) {
    // int64 little-endian with values < 2^31 => all odd 32-bit words zero
    unsigned m = 0;
    for (int k = threadIdx.x; k < 1024; k += 32) m |= e[2 * k + 1];
#pragma unroll
    for (int o = 16; o; o >>= 1) m |= __shfl_down_sync(0xffffffffu, m, o);
    if (threadIdx.x == 0) g_is64 = (m == 0u) ? 1 : 0;
}

// ---------------- 2) histogram of dst ----------------
__global__ void __launch_bounds__(256) hist_kernel(const void* __restrict__ ei) {
    int is64 = __ldg(&g_is64);
    int i = blockIdx.x * blockDim.x + threadIdx.x;
    if (i < NE) {
        int d = load_idx(ei, (long long)NE + i, is64);
        if ((unsigned)d < (unsigned)NN) atomicAdd(&g_cnt[d], 1);
    }
}

// ---------------- 3) decoupled-lookback scan ----------------
__global__ void __launch_bounds__(256) scan_kernel() {
    __shared__ int s_b;
    __shared__ int wsum[8];
    __shared__ int s_off;
    int t = threadIdx.x;
    if (t == 0) s_b = atomicAdd(&g_ticket, 1);
    __syncthreads();
    int b = s_b;
    int lane = t & 31, wid = t >> 5;
    int i = b * 256 + t;

    int c = (i < NN) ? g_cnt[i] : 0;
    int v = c;
#pragma unroll
    for (int o = 1; o < 32; o <<= 1) {
        int n = __shfl_up_sync(0xffffffffu, v, o);
        if (lane >= o) v += n;
    }
    if (lane == 31) wsum[wid] = v;
    __syncthreads();
    if (t < 8) {
        int w = wsum[t];
#pragma unroll
        for (int o = 1; o < 8; o <<= 1) {
            int n = __shfl_up_sync(0xffu, w, o);
            if (t >= o) w += n;
        }
        wsum[t] = w;
    }
    __syncthreads();
    int incl = v + (wid ? wsum[wid - 1] : 0);
    int excl = incl - c;
    int blockTotal = wsum[7];

    if (t == 0) {
        *(volatile unsigned long long*)&g_bpack[b] =
            ((unsigned long long)(unsigned)blockTotal << 32) | 1ull;
    }
    if (t < 32) {
        int sum = 0;
        for (int p = lane; p < b; p += 32) {
            unsigned long long pk;
            do {
                pk = *(volatile unsigned long long*)&g_bpack[p];
            } while ((pk & 1ull) == 0ull);
            sum += (int)(pk >> 32);
        }
#pragma unroll
        for (int o = 16; o; o >>= 1) sum += __shfl_down_sync(0xffffffffu, sum, o);
        if (t == 0) s_off = sum;
    }
    __syncthreads();

    int base = s_off + excl;
    if (i < NN) {
        g_rowstart[i] = base;
        g_cursor[i]   = base;
    }
    if (i == NN - 1) g_rowstart[NN] = base + c;
}

// ---------------- 4) fused: scatter edges | x prescale ----------------
// blocks [0, EDGE_BLOCKS): scatter (needs g_cursor from scan)
// blocks [EDGE_BLOCKS, EDGE_BLOCKS+SCALE_BLOCKS): scale (needs g_cnt from hist)
__global__ void __launch_bounds__(256) scatter_scale_kernel(const void* __restrict__ ei,
                                                            const float4* __restrict__ x) {
    int t = threadIdx.x;
    if (blockIdx.x < EDGE_BLOCKS) {
        int is64 = __ldg(&g_is64);
        int i = blockIdx.x * 256 + t;
        if (i < NE) {
            int s = load_idx(ei, i, is64);
            int d = load_idx(ei, (long long)NE + i, is64);
            if ((unsigned)s < (unsigned)NN && (unsigned)d < (unsigned)NN) {
                int p = atomicAdd(&g_cursor[d], 1);
                g_src_sorted[p] = s;
            }
        }
    } else {
        int idx = (blockIdx.x - EDGE_BLOCKS) * 256 + t;
        int v = idx >> 4, lane = idx & 15;
        if (v >= NN) return;
        float dinv = rsqrtf((float)(g_cnt[v] + 1));
        if (lane == 0) g_dinv[v] = dinv;
        float4 a = x[(size_t)v * 32 + lane * 2];
        float4 b4 = x[(size_t)v * 32 + lane * 2 + 1];
        float f[8] = {a.x, a.y, a.z, a.w, b4.x, b4.y, b4.z, b4.w};
        g_h0h[(size_t)v * 16 + lane] = pack8(f, dinv);
    }
}

// ---------------- 5) hop1: x_hat -> h1_hat (+ restore zero-state) ----------
__global__ void __launch_bounds__(256) prop1_kernel() {
    int g = blockIdx.x * blockDim.x + threadIdx.x;
    // restore zero invariants for next replay (last readers were scan/scale)
    if (g < NN) g_cnt[g] = 0;
    if (g < SCAN_BLOCKS) g_bpack[g] = 0ull;
    if (g == 0) g_ticket = 0;

    int v = g >> 4, lane = g & 15;
    if (v >= NN) return;
    float d = g_dinv[v];
    float sc = d * d;
    float acc[8];
    unpack8(g_h0h[(size_t)v * 16 + lane], acc);
    gather_accum(g_h0h, lane, g_rowstart[v], g_rowstart[v + 1], acc);
    g_h1h[(size_t)v * 16 + lane] = pack8(acc, sc);
}

// ---------------- 6) hop2: h1_hat -> h2 (fp16) ----------------
__global__ void __launch_bounds__(256) prop2_kernel() {
    int g = blockIdx.x * blockDim.x + threadIdx.x;
    int v = g >> 4, lane = g & 15;
    if (v >= NN) return;
    float sc = g_dinv[v];
    float acc[8];
    unpack8(g_h1h[(size_t)v * 16 + lane], acc);
    gather_accum(g_h1h, lane, g_rowstart[v], g_rowstart[v + 1], acc);
    g_h2h[(size_t)v * 16 + lane] = pack8(acc, sc);
}

// ---------------- 7) GEMM: tf32 mma, A exact (from fp16) -> 2 mmas --------
#define AS_STRIDE 132
#define WS_STRIDE 136
#define GEMM_SMEM_BYTES ((64 * AS_STRIDE + 128 * WS_STRIDE) * 4)

__device__ __forceinline__ void mma8(float c[4], const unsigned a[4], const unsigned b[2]) {
    asm volatile(
        "mma.sync.aligned.m16n8k8.row.col.f32.tf32.tf32.f32 "
        "{%0,%1,%2,%3}, {%4,%5,%6,%7}, {%8,%9}, {%0,%1,%2,%3};\n"
        : "+f"(c[0]), "+f"(c[1]), "+f"(c[2]), "+f"(c[3])
        : "r"(a[0]), "r"(a[1]), "r"(a[2]), "r"(a[3]), "r"(b[0]), "r"(b[1]));
}
__device__ __forceinline__ unsigned to_tf32(float x) {
    unsigned h;
    asm("cvt.rna.tf32.f32 %0, %1;" : "=r"(h) : "f"(x));
    return h;
}
__device__ __forceinline__ void split_tf32(float x, unsigned& hi, unsigned& lo) {
    unsigned h = to_tf32(x);
    hi = h;
    lo = __float_as_uint(x - __uint_as_float(h));
}

__global__ void __launch_bounds__(256) gemm_kernel(const float4* __restrict__ Wm,
                                                   const float* __restrict__ bias,
                                                   float* __restrict__ out) {
    extern __shared__ float smem[];
    float* As = smem;                       // [64][AS_STRIDE]
    float* Ws = smem + 64 * AS_STRIDE;      // [128][WS_STRIDE]

    int tid = threadIdx.x;
    int row0 = blockIdx.x * 64;

#pragma unroll
    for (int j = 0; j < 16; j++) {
        int idx = tid + j * 256;
        int r = idx >> 5;
        int c4 = idx & 31;
        float4 w = __ldg(&Wm[idx]);
        *(float4*)&Ws[r * WS_STRIDE + c4 * 4] = w;
    }
    const uint2* A2 = (const uint2*)g_h2h;
#pragma unroll
    for (int j = 0; j < 8; j++) {
        int idx = tid + j * 256;
        int r = idx >> 5;
        int c4 = idx & 31;
        int gr = row0 + r;
        uint2 u = (gr < NN) ? __ldg(&A2[(size_t)gr * 32 + c4]) : make_uint2(0u, 0u);
        float2 f0 = __half22float2(*(__half2*)&u.x);
        float2 f1 = __half22float2(*(__half2*)&u.y);
        float4 a = make_float4(f0.x, f0.y, f1.x, f1.y);
        *(float4*)&As[r * AS_STRIDE + c4 * 4] = a;
    }
    __syncthreads();

    int warp = tid >> 5, lane = tid & 31;
    int mwarp = warp & 1, nwarp = warp >> 1;
    int m0 = mwarp * 32, n0 = nwarp * 32;
    int lr = lane >> 2, lc = lane & 3;

    float c[2][4][4];
#pragma unroll
    for (int mt = 0; mt < 2; mt++)
#pragma unroll
        for (int nt = 0; nt < 4; nt++)
#pragma unroll
            for (int i = 0; i < 4; i++) c[mt][nt][i] = 0.f;

    for (int k0 = 0; k0 < 128; k0 += 8) {
        unsigned ahi[2][4];
#pragma unroll
        for (int mt = 0; mt < 2; mt++) {
            int mb = m0 + mt * 16;
            ahi[mt][0] = to_tf32(As[(mb + lr) * AS_STRIDE + k0 + lc]);
            ahi[mt][1] = to_tf32(As[(mb + lr + 8) * AS_STRIDE + k0 + lc]);
            ahi[mt][2] = to_tf32(As[(mb + lr) * AS_STRIDE + k0 + lc + 4]);
            ahi[mt][3] = to_tf32(As[(mb + lr + 8) * AS_STRIDE + k0 + lc + 4]);
        }
        unsigned bhi[4][2], blo[4][2];
#pragma unroll
        for (int nt = 0; nt < 4; nt++) {
            int nb = n0 + nt * 8;
            float b0 = Ws[(k0 + lc) * WS_STRIDE + nb + lr];
            float b1 = Ws[(k0 + lc + 4) * WS_STRIDE + nb + lr];
            split_tf32(b0, bhi[nt][0], blo[nt][0]);
            split_tf32(b1, bhi[nt][1], blo[nt][1]);
        }
#pragma unroll
        for (int mt = 0; mt < 2; mt++)
#pragma unroll
            for (int nt = 0; nt < 4; nt++) {
                mma8(c[mt][nt], ahi[mt], bhi[nt]);
                mma8(c[mt][nt], ahi[mt], blo[nt]);
            }
    }

#pragma unroll
    for (int mt = 0; mt < 2; mt++) {
#pragma unroll
        for (int nt = 0; nt < 4; nt++) {
            int colBase = n0 + nt * 8 + 2 * lc;
            float b0 = __ldg(&bias[colBase]);
            float b1 = __ldg(&bias[colBase + 1]);
            int r0 = row0 + m0 + mt * 16 + lr;
            int r1 = r0 + 8;
            if (r0 < NN) {
                float2 o = make_float2(c[mt][nt][0] + b0, c[mt][nt][1] + b1);
                *(float2*)&out[(size_t)r0 * DD + colBase] = o;
            }
            if (r1 < NN) {
                float2 o = make_float2(c[mt][nt][2] + b0, c[mt][nt][3] + b1);
                *(float2*)&out[(size_t)r1 * DD + colBase] = o;
            }
        }
    }
}

// ---------------- launch ----------------
extern "C" void kernel_launch(void* const* d_in, const int* in_sizes, int n_in,
                              void* d_out, int out_size) {
    const float* x   = (const float*)d_in[0];
    const void*  ei  = d_in[1];
    const float* Wm  = (const float*)d_in[2];
    const float* bia = (const float*)d_in[3];
    float*       out = (float*)d_out;

    static bool attr_done = false;
    if (!attr_done) {
        cudaFuncSetAttribute(gemm_kernel, cudaFuncAttributeMaxDynamicSharedMemorySize,
                             GEMM_SMEM_BYTES);
        attr_done = true;
    }

    detect_kernel<<<1, 32>>>((const unsigned int*)ei);                 // 1
    hist_kernel<<<EDGE_BLOCKS, 256>>>(ei);                             // 2
    scan_kernel<<<SCAN_BLOCKS, 256>>>();                               // 3
    scatter_scale_kernel<<<EDGE_BLOCKS + SCALE_BLOCKS, 256>>>(ei, (const float4*)x); // 4 (profiled)

    int prop_blocks = (NN * 16 + 255) / 256;
    prop1_kernel<<<prop_blocks, 256>>>();                              // 5
    prop2_kernel<<<prop_blocks, 256>>>();                              // 6
    gemm_kernel<<<(NN + 63) / 64, 256, GEMM_SMEM_BYTES>>>((const float4*)Wm, bia, out); // 7
}